// round 15
// baseline (speedup 1.0000x reference)
#include <cuda_runtime.h>
#include <cuda_fp16.h>
#include <math.h>
#include <stdint.h>

// ---------------------------------------------------------------------------
// Problem constants
// ---------------------------------------------------------------------------
#define BATCH   16
#define CIN     3
#define IMG     256
#define PSZ     16
#define NPATCH  256
#define C5      15
#define PD      3840
#define DMODEL  768
#define DEPTH   8
#define MLP     3072
#define NCLS    1000
#define TTOK    257
#define NT      (BATCH*TTOK)        // 4112
#define NROWS_EMBED (BATCH*NPATCH)  // 4096
#define NHEAD   384

// weight plane offsets (elements)
#define WOFF_SPT  0
#define WSZ_SPT   (PD*DMODEL)
#define WOFF_INP  (WOFF_SPT + WSZ_SPT)
#define WSZ_INP   (DEPTH*DMODEL*3*DMODEL)
#define WOFF_OUTP (WOFF_INP + WSZ_INP)
#define WSZ_OUTP  (DEPTH*DMODEL*DMODEL)
#define WOFF_FF1  (WOFF_OUTP + WSZ_OUTP)
#define WSZ_FF1   (DEPTH*DMODEL*MLP)
#define WOFF_FF2  (WOFF_FF1 + WSZ_FF1)
#define WSZ_FF2   (DEPTH*MLP*DMODEL)
#define WTOT      (WOFF_FF2 + WSZ_FF2)

// ---------------------------------------------------------------------------
// Scratch (device globals) — single fp16 plane everywhere
// ---------------------------------------------------------------------------
__device__ __half g_wh[WTOT];
__device__ __half g_ph[NROWS_EMBED * PD];
__device__ __half g_xnh[NT * DMODEL];
__device__ __half g_oh[NT * DMODEL];
__device__ __half g_hmh[NT * MLP];
__device__ __half g_feat[NT * 3 * DMODEL];
__device__ float g_x[NT * DMODEL];
__device__ float g_lb[DEPTH * DMODEL];
__device__ float g_cls[BATCH * DMODEL];

// ---------------------------------------------------------------------------
// Helpers
// ---------------------------------------------------------------------------
__device__ __forceinline__ uint32_t smem_u32(const void* p) {
    uint32_t a;
    asm("{ .reg .u64 t; cvta.to.shared.u64 t, %1; cvt.u32.u64 %0, t; }"
        : "=r"(a) : "l"(p));
    return a;
}
__device__ __forceinline__ void ldsm4(uint32_t* r, uint32_t addr) {
    asm volatile("ldmatrix.sync.aligned.m8n8.x4.shared.b16 {%0,%1,%2,%3}, [%4];"
                 : "=r"(r[0]), "=r"(r[1]), "=r"(r[2]), "=r"(r[3]) : "r"(addr));
}
__device__ __forceinline__ void ldsm4t(uint32_t* r, uint32_t addr) {
    asm volatile("ldmatrix.sync.aligned.m8n8.x4.trans.shared.b16 {%0,%1,%2,%3}, [%4];"
                 : "=r"(r[0]), "=r"(r[1]), "=r"(r[2]), "=r"(r[3]) : "r"(addr));
}
// fp16-accumulate HMMA: D,C are 2 b32 regs (4 halves)
__device__ __forceinline__ void mma16816h(uint32_t* d, const uint32_t* a, const uint32_t* b) {
    asm volatile(
        "mma.sync.aligned.m16n8k16.row.col.f16.f16.f16.f16 "
        "{%0,%1}, {%2,%3,%4,%5}, {%6,%7}, {%0,%1};"
        : "+r"(d[0]), "+r"(d[1])
        : "r"(a[0]), "r"(a[1]), "r"(a[2]), "r"(a[3]), "r"(b[0]), "r"(b[1]));
}
__device__ __forceinline__ void cpasync16(uint32_t dst, const void* src, uint32_t n) {
    asm volatile("cp.async.cg.shared.global [%0], [%1], 16, %2;"
                 :: "r"(dst), "l"(src), "r"(n) : "memory");
}
__device__ __forceinline__ void cp_commit() {
    asm volatile("cp.async.commit_group;" ::: "memory");
}
template<int N>
__device__ __forceinline__ void cp_wait() {
    asm volatile("cp.async.wait_group %0;" :: "n"(N) : "memory");
}

__device__ __forceinline__ float gelu_exact(float x) {
    return 0.5f * x * (1.f + erff(x * 0.70710678118654752440f));
}

__device__ __forceinline__ float blockReduceSum(float v) {
    __shared__ float sh[32];
    __shared__ float res;
    int lane = threadIdx.x & 31;
    int wid  = threadIdx.x >> 5;
    #pragma unroll
    for (int o = 16; o > 0; o >>= 1) v += __shfl_down_sync(0xffffffffu, v, o);
    if (lane == 0) sh[wid] = v;
    __syncthreads();
    int nw = (blockDim.x + 31) >> 5;
    v = (threadIdx.x < nw) ? sh[threadIdx.x] : 0.f;
    if (wid == 0) {
        #pragma unroll
        for (int o = 16; o > 0; o >>= 1) v += __shfl_down_sync(0xffffffffu, v, o);
        if (lane == 0) res = v;
    }
    __syncthreads();
    return res;
}

__device__ __forceinline__ uint2 cvt4h(float4 v) {
    __half2 a = __floats2half2_rn(v.x, v.y);
    __half2 b = __floats2half2_rn(v.z, v.w);
    return make_uint2(*reinterpret_cast<uint32_t*>(&a), *reinterpret_cast<uint32_t*>(&b));
}

// ---------------------------------------------------------------------------
// Weight pre-conversion: all 5 weight tensors -> single fp16 plane, ONE launch
// ---------------------------------------------------------------------------
__global__ __launch_bounds__(256)
void cvtw_all_k(const float* __restrict__ spt, const float* __restrict__ inp,
                const float* __restrict__ outp, const float* __restrict__ f1,
                const float* __restrict__ f2, __half* __restrict__ h)
{
    size_t i = ((size_t)blockIdx.x * 256 + threadIdx.x) * 4;
    if (i >= WTOT) return;
    const float* src;
    size_t off;
    if (i < WOFF_INP)       { src = spt;  off = i - WOFF_SPT;  }
    else if (i < WOFF_OUTP) { src = inp;  off = i - WOFF_INP;  }
    else if (i < WOFF_FF1)  { src = outp; off = i - WOFF_OUTP; }
    else if (i < WOFF_FF2)  { src = f1;   off = i - WOFF_FF1;  }
    else                    { src = f2;   off = i - WOFF_FF2;  }
    float4 v = *reinterpret_cast<const float4*>(src + off);
    *reinterpret_cast<uint2*>(h + i) = cvt4h(v);
}

// ---------------------------------------------------------------------------
// cls row init
// ---------------------------------------------------------------------------
__global__ void cls_k(const float* __restrict__ cls_token,
                      const float* __restrict__ pos,
                      float* __restrict__ x)
{
    int i = blockIdx.x * blockDim.x + threadIdx.x;
    if (i >= BATCH * DMODEL) return;
    int b = i / DMODEL, d = i - b * DMODEL;
    x[(long)b * TTOK * DMODEL + d] = cls_token[d] + pos[d];
}

// ---------------------------------------------------------------------------
// HMMA GEMM, fp16 single-pass, fp16 accumulate in-chunk (promote every K=64),
// cp.async 4-stage pipeline.
// CTA tile 128x128, K-chunk 32, 8 warps (2m x 4n), warp tile 64x32, 2 CTAs/SM.
// ---------------------------------------------------------------------------
#define EPI_STORE_H    0   // store fp16 (feat)
#define EPI_EMBED      1
#define EPI_RESID      2
#define EPI_GELU_H     3
#define EPI_BIAS_RESID 4

#define NTHREADS 256
#define APITCH 80
#define BPITCH 272
#define OFF_A  0
#define OFF_B  10240
#define SBUF   18944        // 10240 + 32*272
#define STAGES 4
#define SMTOT  (STAGES*SBUF)   // 75776; x2 CTAs = 151552 < 228KB

__device__ __forceinline__ void stage_load(uint32_t sb,
                                           const __half* __restrict__ Ah,
                                           const __half* __restrict__ Bh,
                                           int M, int N, int lda,
                                           int rowBase, int colBase, int s, int tid)
{
    const int k0 = s << 5;
    {
        int row  = tid >> 1;
        int half = tid & 1;
        int gr   = rowBase + row;
        uint32_t nbytes = (gr < M) ? 16u : 0u;
        int grs = (gr < M) ? gr : (M - 1);
        size_t gbase = (size_t)grs * lda + k0 + half * 16;
        uint32_t sbase = (uint32_t)(row * APITCH + half * 32);
        cpasync16(sb + OFF_A + sbase,      Ah + gbase,     nbytes);
        cpasync16(sb + OFF_A + sbase + 16, Ah + gbase + 8, nbytes);
    }
    #pragma unroll
    for (int i = 0; i < 2; i++) {
        int idx = tid + i * 256;
        int row = idx >> 4;
        int seg = idx & 15;
        size_t goff = (size_t)(k0 + row) * N + colBase + seg * 8;
        uint32_t so = (uint32_t)(row * BPITCH + seg * 16);
        cpasync16(sb + OFF_B + so, Bh + goff, 16u);
    }
}

// accumulate one chunk into fp16 accumulators
__device__ __forceinline__ void compute_chunk_h(uint32_t sbuf, int lane, int wm, int wn,
                                                uint32_t hacc[4][4][2])
{
    #pragma unroll
    for (int k16 = 0; k16 < 32; k16 += 16) {
        const uint32_t arow = (uint32_t)(wm + (lane & 7) + (lane & 8));
        const uint32_t aoff = arow * APITCH + (uint32_t)(k16 + ((lane & 16) >> 1)) * 2;
        const uint32_t brow = (uint32_t)(k16 + (lane & 7) + ((lane & 16) >> 1));
        const uint32_t boff = brow * BPITCH + (uint32_t)(wn + (lane & 8)) * 2;

        uint32_t bH[2][4];
        ldsm4t(bH[0], sbuf + OFF_B + boff);
        ldsm4t(bH[1], sbuf + OFF_B + boff + 32);

        #pragma unroll
        for (int mb = 0; mb < 4; mb++) {
            uint32_t a[4];
            ldsm4(a, sbuf + OFF_A + aoff + mb * 16 * APITCH);
            #pragma unroll
            for (int nb = 0; nb < 4; nb++) {
                uint32_t bb[2] = { bH[nb >> 1][nb & 1], bH[nb >> 1][(nb & 1) + 2] };
                mma16816h(hacc[mb][nb], a, bb);
            }
        }
    }
}

template<int EPI>
__global__ __launch_bounds__(NTHREADS, 2)
void mmagemm_k(const __half* __restrict__ Ah, const __half* __restrict__ Bh,
               void* __restrict__ Cv,
               const float* __restrict__ bias, const float* __restrict__ extra,
               int M, int N, int K)
{
    extern __shared__ char smem[];
    const uint32_t sbase = smem_u32(smem);
    const int tid  = threadIdx.x;
    const int lane = tid & 31;
    const int wid  = tid >> 5;
    const int wm   = (wid >> 2) * 64;
    const int wn   = (wid & 3) * 32;
    const int rowBase = blockIdx.y * 128;
    const int colBase = blockIdx.x * 128;
    const int nc = K >> 5;        // always even for our shapes

    float acc[4][4][4];
    #pragma unroll
    for (int a = 0; a < 4; a++)
        #pragma unroll
        for (int b = 0; b < 4; b++)
            #pragma unroll
            for (int c = 0; c < 4; c++) acc[a][b][c] = 0.f;

    uint32_t hacc[4][4][2];

    #pragma unroll
    for (int s = 0; s < STAGES - 1; s++) {
        if (s < nc)
            stage_load(sbase + s * SBUF, Ah, Bh, M, N, K, rowBase, colBase, s, tid);
        cp_commit();
    }

    for (int c = 0; c < nc; c++) {
        cp_wait<STAGES - 2>();
        __syncthreads();
        int s = c + STAGES - 1;
        if (s < nc)
            stage_load(sbase + (s % STAGES) * SBUF, Ah, Bh, M, N, K,
                       rowBase, colBase, s, tid);
        cp_commit();
        if ((c & 1) == 0) {
            #pragma unroll
            for (int a = 0; a < 4; a++)
                #pragma unroll
                for (int b = 0; b < 4; b++) { hacc[a][b][0] = 0u; hacc[a][b][1] = 0u; }
        }
        compute_chunk_h(sbase + (c % STAGES) * SBUF, lane, wm, wn, hacc);
        if ((c & 1) == 1) {
            #pragma unroll
            for (int a = 0; a < 4; a++)
                #pragma unroll
                for (int b = 0; b < 4; b++) {
                    float2 lo = __half22float2(*reinterpret_cast<__half2*>(&hacc[a][b][0]));
                    float2 hi = __half22float2(*reinterpret_cast<__half2*>(&hacc[a][b][1]));
                    acc[a][b][0] += lo.x;
                    acc[a][b][1] += lo.y;
                    acc[a][b][2] += hi.x;
                    acc[a][b][3] += hi.y;
                }
        }
    }

    // ---- epilogue ----
    const int mrow = rowBase + wm + (lane >> 2);
    const int mcol = colBase + wn + ((lane & 3) << 1);
    #pragma unroll
    for (int mi = 0; mi < 4; mi++) {
        #pragma unroll
        for (int hf = 0; hf < 2; hf++) {
            const int row = mrow + mi * 16 + hf * 8;
            if (row >= M) continue;
            #pragma unroll
            for (int ni = 0; ni < 4; ni++) {
                const int col = mcol + ni * 8;
                float v0 = acc[mi][ni][hf * 2];
                float v1 = acc[mi][ni][hf * 2 + 1];
                if (EPI == EPI_STORE_H) {
                    __half* C = (__half*)Cv;
                    *reinterpret_cast<__half2*>(C + (size_t)row * N + col) =
                        __floats2half2_rn(v0, v1);
                } else if (EPI == EPI_EMBED) {
                    float* C = (float*)Cv;
                    int b  = row >> 8;
                    int tl = row & 255;
                    float2 bb = *reinterpret_cast<const float2*>(bias + col);
                    float2 pp = *reinterpret_cast<const float2*>(extra + (size_t)(tl + 1) * N + col);
                    *reinterpret_cast<float2*>(C + ((size_t)b * TTOK + 1 + tl) * N + col) =
                        make_float2(v0 + bb.x + pp.x, v1 + bb.y + pp.y);
                } else if (EPI == EPI_RESID) {
                    float* C = (float*)Cv;
                    float2* o = reinterpret_cast<float2*>(C + (size_t)row * N + col);
                    float2 cc = *o;
                    *o = make_float2(cc.x + v0, cc.y + v1);
                } else if (EPI == EPI_GELU_H) {
                    __half* Hh = (__half*)Cv;
                    float2 bb = *reinterpret_cast<const float2*>(bias + col);
                    __half2 g = __floats2half2_rn(gelu_exact(v0 + bb.x),
                                                  gelu_exact(v1 + bb.y));
                    *reinterpret_cast<__half2*>(Hh + (size_t)row * N + col) = g;
                } else if (EPI == EPI_BIAS_RESID) {
                    float* C = (float*)Cv;
                    float2 bb = *reinterpret_cast<const float2*>(bias + col);
                    float2* o = reinterpret_cast<float2*>(C + (size_t)row * N + col);
                    float2 cc = *o;
                    *o = make_float2(cc.x + v0 + bb.x, cc.y + v1 + bb.y);
                }
            }
        }
    }
}

// ---------------------------------------------------------------------------
// Shifted-patch extraction + LayerNorm -> fp16 plane
// ---------------------------------------------------------------------------
__global__ __launch_bounds__(256)
void patchln_k(const float* __restrict__ img,
               const float* __restrict__ ln_g,
               const float* __restrict__ ln_b,
               __half* __restrict__ ph)
{
    const int blk = blockIdx.x;
    const int b   = blk >> 8;
    const int pt  = blk & 255;
    const int phh = pt >> 4;
    const int pw  = pt & 15;

    __shared__ float vals[PD];

    const int sh_tab[5] = {0, 0, 0, 1, -1};
    const int sw_tab[5] = {0, 1, -1, 0, 0};

    float s = 0.f, ss = 0.f;
    for (int f = threadIdx.x; f < PD; f += 256) {
        int py  = f / (PSZ * C5);
        int rem = f - py * (PSZ * C5);
        int px  = rem / C5;
        int c   = rem - px * C5;
        int g   = c / CIN;
        int ch  = c - g * CIN;
        int row = phh * PSZ + py - sh_tab[g];
        int col = pw * PSZ + px - sw_tab[g];
        float v = 0.f;
        if (row >= 0 && row < IMG && col >= 0 && col < IMG)
            v = img[(((long)b * CIN + ch) * IMG + row) * IMG + col];
        vals[f] = v;
        s  += v;
        ss += v * v;
    }
    float tsum  = blockReduceSum(s);
    float tsum2 = blockReduceSum(ss);
    float mean  = tsum * (1.f / PD);
    float var   = tsum2 * (1.f / PD) - mean * mean;
    float rstd  = rsqrtf(var + 1e-5f);
    __syncthreads();
    size_t rowoff = (size_t)blk * PD;
    for (int f = threadIdx.x; f < PD; f += 256) {
        float y = (vals[f] - mean) * rstd * ln_g[f] + ln_b[f];
        ph[rowoff + f] = __float2half_rn(y);
    }
}

// ---------------------------------------------------------------------------
__global__ void lb_k(const float* __restrict__ lbin, float* __restrict__ lbout)
{
    int d = blockIdx.x * blockDim.x + threadIdx.x;
    if (d >= DMODEL) return;
    float v[DEPTH];
    float m = -1e30f;
    #pragma unroll
    for (int i = 0; i < DEPTH; i++) { v[i] = lbin[i * DMODEL + d]; m = fmaxf(m, v[i]); }
    float s = 0.f;
    #pragma unroll
    for (int i = 0; i < DEPTH; i++) { v[i] = expf(v[i] - m); s += v[i]; }
    float inv = 1.f / s;
    float c = 0.f;
    float c0 = v[0] * inv;
    #pragma unroll
    for (int i = 0; i < DEPTH; i++) { c += v[i] * inv; lbout[i * DMODEL + d] = c - c0; }
}

// RMSNorm -> fp16 plane
__global__ __launch_bounds__(256)
void rmsnorm_k(const float* __restrict__ x, __half* __restrict__ yh)
{
    const long row = blockIdx.x;
    const float* xr = x + row * DMODEL;
    float s = 0.f;
    for (int i = threadIdx.x; i < DMODEL; i += 256) { float v = xr[i]; s += v * v; }
    float tot = blockReduceSum(s);
    float r = rsqrtf(tot * (1.f / DMODEL) + 1e-6f);
    size_t off = (size_t)row * DMODEL;
    for (int i = threadIdx.x; i < DMODEL; i += 256)
        yh[off + i] = __float2half_rn(xr[i] * r);
}

// hGRU2 scan (reads fp16 feat) -> fp16 plane
__global__ __launch_bounds__(256)
void hgru_k(const __half* __restrict__ feat, const float* __restrict__ lb,
            __half* __restrict__ oh)
{
    int e = blockIdx.x * blockDim.x + threadIdx.x;
    if (e >= TTOK * NHEAD) return;
    int t = e / NHEAD;
    int h = e - t * NHEAD;

    float lb0 = lb[2 * h];
    float lb1 = lb[2 * h + 1];
    float S00 = 0.f, S01 = 0.f, S10 = 0.f, S11 = 0.f;

    #pragma unroll 1
    for (int n = 0; n < BATCH; n++) {
        const __half* r = feat + (size_t)(n * TTOK + t) * (3 * DMODEL);
        float2 vv = __half22float2(*(const __half2*)(r + 2 * h));
        float2 qq = __half22float2(*(const __half2*)(r + DMODEL + 2 * h));
        float2 ff = __half22float2(*(const __half2*)(r + 2 * DMODEL + 2 * h));
        float v0 = gelu_exact(vv.x), v1 = gelu_exact(vv.y);
        float q0 = gelu_exact(qq.x), q1 = gelu_exact(qq.y);
        float s0 = 1.f / (1.f + expf(-ff.x));
        float s1 = 1.f / (1.f + expf(-ff.y));
        float lam0 = lb0 + (1.f - lb0) * s0;
        float lam1 = lb1 + (1.f - lb1) * s1;
        float k0 = 1.f - lam0, k1 = 1.f - lam1;
        S00 = lam0 * S00 + k0 * v0;  S01 = lam0 * S01 + k0 * v1;
        S10 = lam1 * S10 + k1 * v0;  S11 = lam1 * S11 + k1 * v1;
        float o0 = q0 * S00 + q1 * S10;
        float o1 = q0 * S01 + q1 * S11;
        __half2 p = __floats2half2_rn(o0, o1);
        *reinterpret_cast<__half2*>(oh + (size_t)(n * TTOK + t) * DMODEL + 2 * h) = p;
    }
}

__global__ __launch_bounds__(256)
void final_k(const float* __restrict__ x,
             const float* __restrict__ g, const float* __restrict__ bvec,
             float* __restrict__ cls)
{
    int b = blockIdx.x;
    const float* xr = x + (long)b * TTOK * DMODEL;
    __shared__ float y[DMODEL];
    float s = 0.f, ss = 0.f;
    for (int i = threadIdx.x; i < DMODEL; i += 256) {
        float v = xr[i];
        y[i] = v;
        s  += v;
        ss += v * v;
    }
    float tsum  = blockReduceSum(s);
    float tsum2 = blockReduceSum(ss);
    float rstd1 = rsqrtf(tsum2 * (1.f / DMODEL) + 1e-6f);
    float mean  = rstd1 * tsum * (1.f / DMODEL);
    float ez2   = rstd1 * rstd1 * tsum2 * (1.f / DMODEL);
    float var   = ez2 - mean * mean;
    float rstd2 = rsqrtf(var + 1e-5f);
    __syncthreads();
    for (int i = threadIdx.x; i < DMODEL; i += 256) {
        float z = y[i] * rstd1;
        cls[(long)b * DMODEL + i] = (z - mean) * rstd2 * g[i] + bvec[i];
    }
}

__global__ __launch_bounds__(256)
void head_k(const float* __restrict__ cls, const float* __restrict__ w,
            const float* __restrict__ bias, float* __restrict__ out)
{
    int idx = blockIdx.x * blockDim.x + threadIdx.x;
    if (idx >= BATCH * NCLS) return;
    int b = idx / NCLS, c = idx - b * NCLS;
    const float* xr = cls + (long)b * DMODEL;
    float s = bias[c];
    #pragma unroll 4
    for (int k = 0; k < DMODEL; k++)
        s = fmaf(xr[k], w[(long)k * NCLS + c], s);
    out[idx] = s;
}

// ---------------------------------------------------------------------------
// Launch
// ---------------------------------------------------------------------------
extern "C" void kernel_launch(void* const* d_in, const int* in_sizes, int n_in,
                              void* d_out, int out_size)
{
    const float* img          = (const float*)d_in[0];
    const float* spt_ln_g     = (const float*)d_in[1];
    const float* spt_ln_b     = (const float*)d_in[2];
    const float* spt_w        = (const float*)d_in[3];
    const float* spt_b        = (const float*)d_in[4];
    const float* pos_emb      = (const float*)d_in[5];
    const float* cls_token    = (const float*)d_in[6];
    const float* lower_bounds = (const float*)d_in[7];
    const float* in_proj_w    = (const float*)d_in[8];
    const float* out_proj_w   = (const float*)d_in[9];
    const float* ff_w1        = (const float*)d_in[10];
    const float* ff_b1        = (const float*)d_in[11];
    const float* ff_w2        = (const float*)d_in[12];
    const float* ff_b2        = (const float*)d_in[13];
    const float* head_ln_g    = (const float*)d_in[14];
    const float* head_ln_b    = (const float*)d_in[15];
    const float* head_w       = (const float*)d_in[16];
    const float* head_b       = (const float*)d_in[17];

    __half *wh, *ph, *xnh, *oh, *hmh, *feat;
    float *x, *lb, *cls;
    cudaGetSymbolAddress((void**)&wh,   g_wh);
    cudaGetSymbolAddress((void**)&ph,   g_ph);
    cudaGetSymbolAddress((void**)&xnh,  g_xnh);
    cudaGetSymbolAddress((void**)&oh,   g_oh);
    cudaGetSymbolAddress((void**)&hmh,  g_hmh);
    cudaGetSymbolAddress((void**)&feat, g_feat);
    cudaGetSymbolAddress((void**)&x,    g_x);
    cudaGetSymbolAddress((void**)&lb,   g_lb);
    cudaGetSymbolAddress((void**)&cls,  g_cls);

    static bool attr_done = false;
    if (!attr_done) {
        cudaFuncSetAttribute(mmagemm_k<EPI_STORE_H>,    cudaFuncAttributeMaxDynamicSharedMemorySize, SMTOT);
        cudaFuncSetAttribute(mmagemm_k<EPI_EMBED>,      cudaFuncAttributeMaxDynamicSharedMemorySize, SMTOT);
        cudaFuncSetAttribute(mmagemm_k<EPI_RESID>,      cudaFuncAttributeMaxDynamicSharedMemorySize, SMTOT);
        cudaFuncSetAttribute(mmagemm_k<EPI_GELU_H>,     cudaFuncAttributeMaxDynamicSharedMemorySize, SMTOT);
        cudaFuncSetAttribute(mmagemm_k<EPI_BIAS_RESID>, cudaFuncAttributeMaxDynamicSharedMemorySize, SMTOT);
        attr_done = true;
    }

    patchln_k<<<NROWS_EMBED, 256>>>(img, spt_ln_g, spt_ln_b, ph);
    cvtw_all_k<<<(int)((WTOT / 4 + 255) / 256), 256>>>(spt_w, in_proj_w, out_proj_w,
                                                       ff_w1, ff_w2, wh);
    cls_k<<<(BATCH * DMODEL + 255) / 256, 256>>>(cls_token, pos_emb, x);
    {
        dim3 grid(DMODEL / 128, NROWS_EMBED / 128);
        mmagemm_k<EPI_EMBED><<<grid, NTHREADS, SMTOT>>>(
            ph, wh + WOFF_SPT, x, spt_b, pos_emb, NROWS_EMBED, DMODEL, PD);
    }
    lb_k<<<(DMODEL + 255) / 256, 256>>>(lower_bounds, lb);

    for (int i = 0; i < DEPTH; i++) {
        rmsnorm_k<<<NT, 256>>>(x, xnh);
        {
            dim3 grid((3 * DMODEL) / 128, (NT + 127) / 128);
            mmagemm_k<EPI_STORE_H><<<grid, NTHREADS, SMTOT>>>(
                xnh, wh + WOFF_INP + (size_t)i * DMODEL * 3 * DMODEL,
                feat, nullptr, nullptr, NT, 3 * DMODEL, DMODEL);
        }
        hgru_k<<<(TTOK * NHEAD + 255) / 256, 256>>>(feat, lb + (size_t)i * DMODEL, oh);
        {
            dim3 grid(DMODEL / 128, (NT + 127) / 128);
            mmagemm_k<EPI_RESID><<<grid, NTHREADS, SMTOT>>>(
                oh, wh + WOFF_OUTP + (size_t)i * DMODEL * DMODEL,
                x, nullptr, nullptr, NT, DMODEL, DMODEL);
        }
        rmsnorm_k<<<NT, 256>>>(x, xnh);
        {
            dim3 grid(MLP / 128, (NT + 127) / 128);
            mmagemm_k<EPI_GELU_H><<<grid, NTHREADS, SMTOT>>>(
                xnh, wh + WOFF_FF1 + (size_t)i * DMODEL * MLP,
                hmh, ff_b1 + (size_t)i * MLP, nullptr, NT, MLP, DMODEL);
        }
        {
            dim3 grid(DMODEL / 128, (NT + 127) / 128);
            mmagemm_k<EPI_BIAS_RESID><<<grid, NTHREADS, SMTOT>>>(
                hmh, wh + WOFF_FF2 + (size_t)i * MLP * DMODEL,
                x, ff_b2 + (size_t)i * DMODEL, nullptr, NT, DMODEL, MLP);
        }
    }

    final_k<<<BATCH, 256>>>(x, head_ln_g, head_ln_b, cls);
    head_k<<<(BATCH * NCLS + 255) / 256, 256>>>(cls, head_w, head_b, (float*)d_out);
}

// round 16
// speedup vs baseline: 1.1007x; 1.1007x over previous
#include <cuda_runtime.h>
#include <cuda_fp16.h>
#include <math.h>
#include <stdint.h>

// ---------------------------------------------------------------------------
// Problem constants
// ---------------------------------------------------------------------------
#define BATCH   16
#define CIN     3
#define IMG     256
#define PSZ     16
#define NPATCH  256
#define C5      15
#define PD      3840
#define DMODEL  768
#define DEPTH   8
#define MLP     3072
#define NCLS    1000
#define TTOK    257
#define NT      (BATCH*TTOK)        // 4112
#define NROWS_EMBED (BATCH*NPATCH)  // 4096
#define NHEAD   384

// weight plane offsets (elements)
#define WOFF_SPT  0
#define WSZ_SPT   (PD*DMODEL)
#define WOFF_INP  (WOFF_SPT + WSZ_SPT)
#define WSZ_INP   (DEPTH*DMODEL*3*DMODEL)
#define WOFF_OUTP (WOFF_INP + WSZ_INP)
#define WSZ_OUTP  (DEPTH*DMODEL*DMODEL)
#define WOFF_FF1  (WOFF_OUTP + WSZ_OUTP)
#define WSZ_FF1   (DEPTH*DMODEL*MLP)
#define WOFF_FF2  (WOFF_FF1 + WSZ_FF1)
#define WSZ_FF2   (DEPTH*MLP*DMODEL)
#define WTOT      (WOFF_FF2 + WSZ_FF2)

// ---------------------------------------------------------------------------
// Scratch (device globals) — single fp16 plane everywhere
// ---------------------------------------------------------------------------
__device__ __half g_wh[WTOT];
__device__ __half g_ph[NROWS_EMBED * PD];
__device__ __half g_xnh[NT * DMODEL];
__device__ __half g_oh[NT * DMODEL];
__device__ __half g_hmh[NT * MLP];
__device__ __half g_feat[NT * 3 * DMODEL];
__device__ float g_x[NT * DMODEL];
__device__ float g_lb[DEPTH * DMODEL];
__device__ float g_cls[BATCH * DMODEL];

// ---------------------------------------------------------------------------
// Helpers
// ---------------------------------------------------------------------------
__device__ __forceinline__ uint32_t smem_u32(const void* p) {
    uint32_t a;
    asm("{ .reg .u64 t; cvta.to.shared.u64 t, %1; cvt.u32.u64 %0, t; }"
        : "=r"(a) : "l"(p));
    return a;
}
__device__ __forceinline__ void ldsm4(uint32_t* r, uint32_t addr) {
    asm volatile("ldmatrix.sync.aligned.m8n8.x4.shared.b16 {%0,%1,%2,%3}, [%4];"
                 : "=r"(r[0]), "=r"(r[1]), "=r"(r[2]), "=r"(r[3]) : "r"(addr));
}
__device__ __forceinline__ void ldsm4t(uint32_t* r, uint32_t addr) {
    asm volatile("ldmatrix.sync.aligned.m8n8.x4.trans.shared.b16 {%0,%1,%2,%3}, [%4];"
                 : "=r"(r[0]), "=r"(r[1]), "=r"(r[2]), "=r"(r[3]) : "r"(addr));
}
__device__ __forceinline__ void mma16816(float* d, const uint32_t* a, const uint32_t* b) {
    asm volatile(
        "mma.sync.aligned.m16n8k16.row.col.f32.f16.f16.f32 "
        "{%0,%1,%2,%3}, {%4,%5,%6,%7}, {%8,%9}, {%0,%1,%2,%3};"
        : "+f"(d[0]), "+f"(d[1]), "+f"(d[2]), "+f"(d[3])
        : "r"(a[0]), "r"(a[1]), "r"(a[2]), "r"(a[3]), "r"(b[0]), "r"(b[1]));
}
__device__ __forceinline__ void cpasync16(uint32_t dst, const void* src, uint32_t n) {
    asm volatile("cp.async.cg.shared.global [%0], [%1], 16, %2;"
                 :: "r"(dst), "l"(src), "r"(n) : "memory");
}
__device__ __forceinline__ void cp_commit() {
    asm volatile("cp.async.commit_group;" ::: "memory");
}
template<int N>
__device__ __forceinline__ void cp_wait() {
    asm volatile("cp.async.wait_group %0;" :: "n"(N) : "memory");
}

__device__ __forceinline__ float gelu_exact(float x) {
    return 0.5f * x * (1.f + erff(x * 0.70710678118654752440f));
}

__device__ __forceinline__ float blockReduceSum(float v) {
    __shared__ float sh[32];
    __shared__ float res;
    int lane = threadIdx.x & 31;
    int wid  = threadIdx.x >> 5;
    #pragma unroll
    for (int o = 16; o > 0; o >>= 1) v += __shfl_down_sync(0xffffffffu, v, o);
    if (lane == 0) sh[wid] = v;
    __syncthreads();
    int nw = (blockDim.x + 31) >> 5;
    v = (threadIdx.x < nw) ? sh[threadIdx.x] : 0.f;
    if (wid == 0) {
        #pragma unroll
        for (int o = 16; o > 0; o >>= 1) v += __shfl_down_sync(0xffffffffu, v, o);
        if (lane == 0) res = v;
    }
    __syncthreads();
    return res;
}

__device__ __forceinline__ uint2 cvt4h(float4 v) {
    __half2 a = __floats2half2_rn(v.x, v.y);
    __half2 b = __floats2half2_rn(v.z, v.w);
    return make_uint2(*reinterpret_cast<uint32_t*>(&a), *reinterpret_cast<uint32_t*>(&b));
}

// ---------------------------------------------------------------------------
// Weight pre-conversion: all 5 weight tensors -> single fp16 plane, ONE launch
// ---------------------------------------------------------------------------
__global__ __launch_bounds__(256)
void cvtw_all_k(const float* __restrict__ spt, const float* __restrict__ inp,
                const float* __restrict__ outp, const float* __restrict__ f1,
                const float* __restrict__ f2, __half* __restrict__ h)
{
    size_t i = ((size_t)blockIdx.x * 256 + threadIdx.x) * 4;
    if (i >= WTOT) return;
    const float* src;
    size_t off;
    if (i < WOFF_INP)       { src = spt;  off = i - WOFF_SPT;  }
    else if (i < WOFF_OUTP) { src = inp;  off = i - WOFF_INP;  }
    else if (i < WOFF_FF1)  { src = outp; off = i - WOFF_OUTP; }
    else if (i < WOFF_FF2)  { src = f1;   off = i - WOFF_FF1;  }
    else                    { src = f2;   off = i - WOFF_FF2;  }
    float4 v = *reinterpret_cast<const float4*>(src + off);
    *reinterpret_cast<uint2*>(h + i) = cvt4h(v);
}

// ---------------------------------------------------------------------------
// cls row init
// ---------------------------------------------------------------------------
__global__ void cls_k(const float* __restrict__ cls_token,
                      const float* __restrict__ pos,
                      float* __restrict__ x)
{
    int i = blockIdx.x * blockDim.x + threadIdx.x;
    if (i >= BATCH * DMODEL) return;
    int b = i / DMODEL, d = i - b * DMODEL;
    x[(long)b * TTOK * DMODEL + d] = cls_token[d] + pos[d];
}

// ---------------------------------------------------------------------------
// HMMA GEMM, fp16 single-pass, cp.async 5-stage pipeline.
// CTA tile 128x128, K-chunk 32, 8 warps (2m x 4n), warp tile 64x32, 2 CTAs/SM.
// ---------------------------------------------------------------------------
#define EPI_STORE_H    0   // store fp16 (feat)
#define EPI_EMBED      1
#define EPI_RESID      2
#define EPI_GELU_H     3
#define EPI_BIAS_RESID 4

#define NTHREADS 256
#define APITCH 80
#define BPITCH 272
#define OFF_A  0
#define OFF_B  10240
#define SBUF   18944        // 10240 + 32*272
#define STAGES 5
#define SMTOT  (STAGES*SBUF)   // 94720; x2 CTAs = 189440 < 228KB

__device__ __forceinline__ void stage_load(uint32_t sb,
                                           const __half* __restrict__ Ah,
                                           const __half* __restrict__ Bh,
                                           int M, int N, int lda,
                                           int rowBase, int colBase, int s, int tid)
{
    const int k0 = s << 5;
    // A: 128 rows x 64B; 512 16B chunks / 256 threads = 2 each
    {
        int row  = tid >> 1;
        int half = tid & 1;
        int gr   = rowBase + row;
        uint32_t nbytes = (gr < M) ? 16u : 0u;
        int grs = (gr < M) ? gr : (M - 1);
        size_t gbase = (size_t)grs * lda + k0 + half * 16;
        uint32_t sbase = (uint32_t)(row * APITCH + half * 32);
        cpasync16(sb + OFF_A + sbase,      Ah + gbase,     nbytes);
        cpasync16(sb + OFF_A + sbase + 16, Ah + gbase + 8, nbytes);
    }
    // B: 32 rows x 256B; 512 chunks / 256 threads = 2 each
    #pragma unroll
    for (int i = 0; i < 2; i++) {
        int idx = tid + i * 256;
        int row = idx >> 4;
        int seg = idx & 15;
        size_t goff = (size_t)(k0 + row) * N + colBase + seg * 8;
        uint32_t so = (uint32_t)(row * BPITCH + seg * 16);
        cpasync16(sb + OFF_B + so, Bh + goff, 16u);
    }
}

__device__ __forceinline__ void compute_chunk(uint32_t sbuf, int lane, int wm, int wn,
                                              float acc[4][4][4])
{
    #pragma unroll
    for (int k16 = 0; k16 < 32; k16 += 16) {
        const uint32_t arow = (uint32_t)(wm + (lane & 7) + (lane & 8));
        const uint32_t aoff = arow * APITCH + (uint32_t)(k16 + ((lane & 16) >> 1)) * 2;
        const uint32_t brow = (uint32_t)(k16 + (lane & 7) + ((lane & 16) >> 1));
        const uint32_t boff = brow * BPITCH + (uint32_t)(wn + (lane & 8)) * 2;

        uint32_t bH[2][4];
        ldsm4t(bH[0], sbuf + OFF_B + boff);
        ldsm4t(bH[1], sbuf + OFF_B + boff + 32);

        #pragma unroll
        for (int mb = 0; mb < 4; mb++) {
            uint32_t a[4];
            ldsm4(a, sbuf + OFF_A + aoff + mb * 16 * APITCH);
            #pragma unroll
            for (int nb = 0; nb < 4; nb++) {
                uint32_t bb[2] = { bH[nb >> 1][nb & 1], bH[nb >> 1][(nb & 1) + 2] };
                mma16816(acc[mb][nb], a, bb);
            }
        }
    }
}

template<int EPI>
__global__ __launch_bounds__(NTHREADS, 2)
void mmagemm_k(const __half* __restrict__ Ah, const __half* __restrict__ Bh,
               void* __restrict__ Cv,
               const float* __restrict__ bias, const float* __restrict__ extra,
               int M, int N, int K)
{
    extern __shared__ char smem[];
    const uint32_t sbase = smem_u32(smem);
    const int tid  = threadIdx.x;
    const int lane = tid & 31;
    const int wid  = tid >> 5;
    const int wm   = (wid >> 2) * 64;   // 2 m-warps
    const int wn   = (wid & 3) * 32;    // 4 n-warps
    const int rowBase = blockIdx.y * 128;
    const int colBase = blockIdx.x * 128;
    const int nc = K >> 5;

    float acc[4][4][4];
    #pragma unroll
    for (int a = 0; a < 4; a++)
        #pragma unroll
        for (int b = 0; b < 4; b++)
            #pragma unroll
            for (int c = 0; c < 4; c++) acc[a][b][c] = 0.f;

    #pragma unroll
    for (int s = 0; s < STAGES - 1; s++) {
        if (s < nc)
            stage_load(sbase + s * SBUF, Ah, Bh, M, N, K, rowBase, colBase, s, tid);
        cp_commit();
    }

    for (int c = 0; c < nc; c++) {
        cp_wait<STAGES - 2>();
        __syncthreads();
        int s = c + STAGES - 1;
        if (s < nc)
            stage_load(sbase + (s % STAGES) * SBUF, Ah, Bh, M, N, K,
                       rowBase, colBase, s, tid);
        cp_commit();
        compute_chunk(sbase + (c % STAGES) * SBUF, lane, wm, wn, acc);
    }

    // ---- epilogue ----
    const int mrow = rowBase + wm + (lane >> 2);
    const int mcol = colBase + wn + ((lane & 3) << 1);
    #pragma unroll
    for (int mi = 0; mi < 4; mi++) {
        #pragma unroll
        for (int hf = 0; hf < 2; hf++) {
            const int row = mrow + mi * 16 + hf * 8;
            if (row >= M) continue;
            #pragma unroll
            for (int ni = 0; ni < 4; ni++) {
                const int col = mcol + ni * 8;
                float v0 = acc[mi][ni][hf * 2];
                float v1 = acc[mi][ni][hf * 2 + 1];
                if (EPI == EPI_STORE_H) {
                    __half* C = (__half*)Cv;
                    *reinterpret_cast<__half2*>(C + (size_t)row * N + col) =
                        __floats2half2_rn(v0, v1);
                } else if (EPI == EPI_EMBED) {
                    float* C = (float*)Cv;
                    int b  = row >> 8;
                    int tl = row & 255;
                    float2 bb = *reinterpret_cast<const float2*>(bias + col);
                    float2 pp = *reinterpret_cast<const float2*>(extra + (size_t)(tl + 1) * N + col);
                    *reinterpret_cast<float2*>(C + ((size_t)b * TTOK + 1 + tl) * N + col) =
                        make_float2(v0 + bb.x + pp.x, v1 + bb.y + pp.y);
                } else if (EPI == EPI_RESID) {
                    float* C = (float*)Cv;
                    float2* o = reinterpret_cast<float2*>(C + (size_t)row * N + col);
                    float2 cc = *o;
                    *o = make_float2(cc.x + v0, cc.y + v1);
                } else if (EPI == EPI_GELU_H) {
                    __half* Hh = (__half*)Cv;
                    float2 bb = *reinterpret_cast<const float2*>(bias + col);
                    __half2 g = __floats2half2_rn(gelu_exact(v0 + bb.x),
                                                  gelu_exact(v1 + bb.y));
                    *reinterpret_cast<__half2*>(Hh + (size_t)row * N + col) = g;
                } else if (EPI == EPI_BIAS_RESID) {
                    float* C = (float*)Cv;
                    float2 bb = *reinterpret_cast<const float2*>(bias + col);
                    float2* o = reinterpret_cast<float2*>(C + (size_t)row * N + col);
                    float2 cc = *o;
                    *o = make_float2(cc.x + v0 + bb.x, cc.y + v1 + bb.y);
                }
            }
        }
    }
}

// ---------------------------------------------------------------------------
// Shifted-patch extraction + LayerNorm -> fp16 plane
// ---------------------------------------------------------------------------
__global__ __launch_bounds__(256)
void patchln_k(const float* __restrict__ img,
               const float* __restrict__ ln_g,
               const float* __restrict__ ln_b,
               __half* __restrict__ ph)
{
    const int blk = blockIdx.x;
    const int b   = blk >> 8;
    const int pt  = blk & 255;
    const int phh = pt >> 4;
    const int pw  = pt & 15;

    __shared__ float vals[PD];

    const int sh_tab[5] = {0, 0, 0, 1, -1};
    const int sw_tab[5] = {0, 1, -1, 0, 0};

    float s = 0.f, ss = 0.f;
    for (int f = threadIdx.x; f < PD; f += 256) {
        int py  = f / (PSZ * C5);
        int rem = f - py * (PSZ * C5);
        int px  = rem / C5;
        int c   = rem - px * C5;
        int g   = c / CIN;
        int ch  = c - g * CIN;
        int row = phh * PSZ + py - sh_tab[g];
        int col = pw * PSZ + px - sw_tab[g];
        float v = 0.f;
        if (row >= 0 && row < IMG && col >= 0 && col < IMG)
            v = img[(((long)b * CIN + ch) * IMG + row) * IMG + col];
        vals[f] = v;
        s  += v;
        ss += v * v;
    }
    float tsum  = blockReduceSum(s);
    float tsum2 = blockReduceSum(ss);
    float mean  = tsum * (1.f / PD);
    float var   = tsum2 * (1.f / PD) - mean * mean;
    float rstd  = rsqrtf(var + 1e-5f);
    __syncthreads();
    size_t rowoff = (size_t)blk * PD;
    for (int f = threadIdx.x; f < PD; f += 256) {
        float y = (vals[f] - mean) * rstd * ln_g[f] + ln_b[f];
        ph[rowoff + f] = __float2half_rn(y);
    }
}

// ---------------------------------------------------------------------------
__global__ void lb_k(const float* __restrict__ lbin, float* __restrict__ lbout)
{
    int d = blockIdx.x * blockDim.x + threadIdx.x;
    if (d >= DMODEL) return;
    float v[DEPTH];
    float m = -1e30f;
    #pragma unroll
    for (int i = 0; i < DEPTH; i++) { v[i] = lbin[i * DMODEL + d]; m = fmaxf(m, v[i]); }
    float s = 0.f;
    #pragma unroll
    for (int i = 0; i < DEPTH; i++) { v[i] = expf(v[i] - m); s += v[i]; }
    float inv = 1.f / s;
    float c = 0.f;
    float c0 = v[0] * inv;
    #pragma unroll
    for (int i = 0; i < DEPTH; i++) { c += v[i] * inv; lbout[i * DMODEL + d] = c - c0; }
}

// RMSNorm -> fp16 plane
__global__ __launch_bounds__(256)
void rmsnorm_k(const float* __restrict__ x, __half* __restrict__ yh)
{
    const long row = blockIdx.x;
    const float* xr = x + row * DMODEL;
    float s = 0.f;
    for (int i = threadIdx.x; i < DMODEL; i += 256) { float v = xr[i]; s += v * v; }
    float tot = blockReduceSum(s);
    float r = rsqrtf(tot * (1.f / DMODEL) + 1e-6f);
    size_t off = (size_t)row * DMODEL;
    for (int i = threadIdx.x; i < DMODEL; i += 256)
        yh[off + i] = __float2half_rn(xr[i] * r);
}

// hGRU2 scan (reads fp16 feat) -> fp16 plane
__global__ __launch_bounds__(256)
void hgru_k(const __half* __restrict__ feat, const float* __restrict__ lb,
            __half* __restrict__ oh)
{
    int e = blockIdx.x * blockDim.x + threadIdx.x;
    if (e >= TTOK * NHEAD) return;
    int t = e / NHEAD;
    int h = e - t * NHEAD;

    float lb0 = lb[2 * h];
    float lb1 = lb[2 * h + 1];
    float S00 = 0.f, S01 = 0.f, S10 = 0.f, S11 = 0.f;

    #pragma unroll 1
    for (int n = 0; n < BATCH; n++) {
        const __half* r = feat + (size_t)(n * TTOK + t) * (3 * DMODEL);
        float2 vv = __half22float2(*(const __half2*)(r + 2 * h));
        float2 qq = __half22float2(*(const __half2*)(r + DMODEL + 2 * h));
        float2 ff = __half22float2(*(const __half2*)(r + 2 * DMODEL + 2 * h));
        float v0 = gelu_exact(vv.x), v1 = gelu_exact(vv.y);
        float q0 = gelu_exact(qq.x), q1 = gelu_exact(qq.y);
        float s0 = 1.f / (1.f + expf(-ff.x));
        float s1 = 1.f / (1.f + expf(-ff.y));
        float lam0 = lb0 + (1.f - lb0) * s0;
        float lam1 = lb1 + (1.f - lb1) * s1;
        float k0 = 1.f - lam0, k1 = 1.f - lam1;
        S00 = lam0 * S00 + k0 * v0;  S01 = lam0 * S01 + k0 * v1;
        S10 = lam1 * S10 + k1 * v0;  S11 = lam1 * S11 + k1 * v1;
        float o0 = q0 * S00 + q1 * S10;
        float o1 = q0 * S01 + q1 * S11;
        __half2 p = __floats2half2_rn(o0, o1);
        *reinterpret_cast<__half2*>(oh + (size_t)(n * TTOK + t) * DMODEL + 2 * h) = p;
    }
}

__global__ __launch_bounds__(256)
void final_k(const float* __restrict__ x,
             const float* __restrict__ g, const float* __restrict__ bvec,
             float* __restrict__ cls)
{
    int b = blockIdx.x;
    const float* xr = x + (long)b * TTOK * DMODEL;
    __shared__ float y[DMODEL];
    float s = 0.f, ss = 0.f;
    for (int i = threadIdx.x; i < DMODEL; i += 256) {
        float v = xr[i];
        y[i] = v;
        s  += v;
        ss += v * v;
    }
    float tsum  = blockReduceSum(s);
    float tsum2 = blockReduceSum(ss);
    float rstd1 = rsqrtf(tsum2 * (1.f / DMODEL) + 1e-6f);
    float mean  = rstd1 * tsum * (1.f / DMODEL);
    float ez2   = rstd1 * rstd1 * tsum2 * (1.f / DMODEL);
    float var   = ez2 - mean * mean;
    float rstd2 = rsqrtf(var + 1e-5f);
    __syncthreads();
    for (int i = threadIdx.x; i < DMODEL; i += 256) {
        float z = y[i] * rstd1;
        cls[(long)b * DMODEL + i] = (z - mean) * rstd2 * g[i] + bvec[i];
    }
}

__global__ __launch_bounds__(256)
void head_k(const float* __restrict__ cls, const float* __restrict__ w,
            const float* __restrict__ bias, float* __restrict__ out)
{
    int idx = blockIdx.x * blockDim.x + threadIdx.x;
    if (idx >= BATCH * NCLS) return;
    int b = idx / NCLS, c = idx - b * NCLS;
    const float* xr = cls + (long)b * DMODEL;
    float s = bias[c];
    #pragma unroll 4
    for (int k = 0; k < DMODEL; k++)
        s = fmaf(xr[k], w[(long)k * NCLS + c], s);
    out[idx] = s;
}

// ---------------------------------------------------------------------------
// Launch
// ---------------------------------------------------------------------------
extern "C" void kernel_launch(void* const* d_in, const int* in_sizes, int n_in,
                              void* d_out, int out_size)
{
    const float* img          = (const float*)d_in[0];
    const float* spt_ln_g     = (const float*)d_in[1];
    const float* spt_ln_b     = (const float*)d_in[2];
    const float* spt_w        = (const float*)d_in[3];
    const float* spt_b        = (const float*)d_in[4];
    const float* pos_emb      = (const float*)d_in[5];
    const float* cls_token    = (const float*)d_in[6];
    const float* lower_bounds = (const float*)d_in[7];
    const float* in_proj_w    = (const float*)d_in[8];
    const float* out_proj_w   = (const float*)d_in[9];
    const float* ff_w1        = (const float*)d_in[10];
    const float* ff_b1        = (const float*)d_in[11];
    const float* ff_w2        = (const float*)d_in[12];
    const float* ff_b2        = (const float*)d_in[13];
    const float* head_ln_g    = (const float*)d_in[14];
    const float* head_ln_b    = (const float*)d_in[15];
    const float* head_w       = (const float*)d_in[16];
    const float* head_b       = (const float*)d_in[17];

    __half *wh, *ph, *xnh, *oh, *hmh, *feat;
    float *x, *lb, *cls;
    cudaGetSymbolAddress((void**)&wh,   g_wh);
    cudaGetSymbolAddress((void**)&ph,   g_ph);
    cudaGetSymbolAddress((void**)&xnh,  g_xnh);
    cudaGetSymbolAddress((void**)&oh,   g_oh);
    cudaGetSymbolAddress((void**)&hmh,  g_hmh);
    cudaGetSymbolAddress((void**)&feat, g_feat);
    cudaGetSymbolAddress((void**)&x,    g_x);
    cudaGetSymbolAddress((void**)&lb,   g_lb);
    cudaGetSymbolAddress((void**)&cls,  g_cls);

    static bool attr_done = false;
    if (!attr_done) {
        cudaFuncSetAttribute(mmagemm_k<EPI_STORE_H>,    cudaFuncAttributeMaxDynamicSharedMemorySize, SMTOT);
        cudaFuncSetAttribute(mmagemm_k<EPI_EMBED>,      cudaFuncAttributeMaxDynamicSharedMemorySize, SMTOT);
        cudaFuncSetAttribute(mmagemm_k<EPI_RESID>,      cudaFuncAttributeMaxDynamicSharedMemorySize, SMTOT);
        cudaFuncSetAttribute(mmagemm_k<EPI_GELU_H>,     cudaFuncAttributeMaxDynamicSharedMemorySize, SMTOT);
        cudaFuncSetAttribute(mmagemm_k<EPI_BIAS_RESID>, cudaFuncAttributeMaxDynamicSharedMemorySize, SMTOT);
        attr_done = true;
    }

    patchln_k<<<NROWS_EMBED, 256>>>(img, spt_ln_g, spt_ln_b, ph);
    cvtw_all_k<<<(int)((WTOT / 4 + 255) / 256), 256>>>(spt_w, in_proj_w, out_proj_w,
                                                       ff_w1, ff_w2, wh);
    cls_k<<<(BATCH * DMODEL + 255) / 256, 256>>>(cls_token, pos_emb, x);
    {
        dim3 grid(DMODEL / 128, NROWS_EMBED / 128);
        mmagemm_k<EPI_EMBED><<<grid, NTHREADS, SMTOT>>>(
            ph, wh + WOFF_SPT, x, spt_b, pos_emb, NROWS_EMBED, DMODEL, PD);
    }
    lb_k<<<(DMODEL + 255) / 256, 256>>>(lower_bounds, lb);

    for (int i = 0; i < DEPTH; i++) {
        rmsnorm_k<<<NT, 256>>>(x, xnh);
        {
            dim3 grid((3 * DMODEL) / 128, (NT + 127) / 128);
            mmagemm_k<EPI_STORE_H><<<grid, NTHREADS, SMTOT>>>(
                xnh, wh + WOFF_INP + (size_t)i * DMODEL * 3 * DMODEL,
                feat, nullptr, nullptr, NT, 3 * DMODEL, DMODEL);
        }
        hgru_k<<<(TTOK * NHEAD + 255) / 256, 256>>>(feat, lb + (size_t)i * DMODEL, oh);
        {
            dim3 grid(DMODEL / 128, (NT + 127) / 128);
            mmagemm_k<EPI_RESID><<<grid, NTHREADS, SMTOT>>>(
                oh, wh + WOFF_OUTP + (size_t)i * DMODEL * DMODEL,
                x, nullptr, nullptr, NT, DMODEL, DMODEL);
        }
        rmsnorm_k<<<NT, 256>>>(x, xnh);
        {
            dim3 grid(MLP / 128, (NT + 127) / 128);
            mmagemm_k<EPI_GELU_H><<<grid, NTHREADS, SMTOT>>>(
                xnh, wh + WOFF_FF1 + (size_t)i * DMODEL * MLP,
                hmh, ff_b1 + (size_t)i * MLP, nullptr, NT, MLP, DMODEL);
        }
        {
            dim3 grid(DMODEL / 128, (NT + 127) / 128);
            mmagemm_k<EPI_BIAS_RESID><<<grid, NTHREADS, SMTOT>>>(
                hmh, wh + WOFF_FF2 + (size_t)i * MLP * DMODEL,
                x, ff_b2 + (size_t)i * DMODEL, nullptr, NT, DMODEL, MLP);
        }
    }

    final_k<<<BATCH, 256>>>(x, head_ln_g, head_ln_b, cls);
    head_k<<<(BATCH * NCLS + 255) / 256, 256>>>(cls, head_w, head_b, (float*)d_out);
}

// round 17
// speedup vs baseline: 1.2880x; 1.1702x over previous
#include <cuda_runtime.h>
#include <cuda_fp16.h>
#include <math.h>
#include <stdint.h>

// ---------------------------------------------------------------------------
// Problem constants
// ---------------------------------------------------------------------------
#define BATCH   16
#define CIN     3
#define IMG     256
#define PSZ     16
#define NPATCH  256
#define C5      15
#define PD      3840
#define DMODEL  768
#define DEPTH   8
#define MLP     3072
#define NCLS    1000
#define TTOK    257
#define NT      (BATCH*TTOK)        // 4112
#define NROWS_EMBED (BATCH*NPATCH)  // 4096
#define NHEAD   384

// weight plane offsets (elements)
#define WOFF_SPT  0
#define WSZ_SPT   (PD*DMODEL)
#define WOFF_INP  (WOFF_SPT + WSZ_SPT)
#define WSZ_INP   (DEPTH*DMODEL*3*DMODEL)
#define WOFF_OUTP (WOFF_INP + WSZ_INP)
#define WSZ_OUTP  (DEPTH*DMODEL*DMODEL)
#define WOFF_FF1  (WOFF_OUTP + WSZ_OUTP)
#define WSZ_FF1   (DEPTH*DMODEL*MLP)
#define WOFF_FF2  (WOFF_FF1 + WSZ_FF1)
#define WSZ_FF2   (DEPTH*MLP*DMODEL)
#define WTOT      (WOFF_FF2 + WSZ_FF2)

// ---------------------------------------------------------------------------
// Scratch (device globals) — single fp16 plane everywhere
// ---------------------------------------------------------------------------
__device__ __half g_wh[WTOT];
__device__ __half g_ph[NROWS_EMBED * PD];
__device__ __half g_xnh[NT * DMODEL];
__device__ __half g_oh[NT * DMODEL];
__device__ __half g_hmh[NT * MLP];
__device__ __half g_feat[NT * 3 * DMODEL];
__device__ float g_x[NT * DMODEL];
__device__ float g_lb[DEPTH * DMODEL];
__device__ float g_cls[BATCH * DMODEL];

// ---------------------------------------------------------------------------
// Helpers
// ---------------------------------------------------------------------------
__device__ __forceinline__ uint32_t smem_u32(const void* p) {
    uint32_t a;
    asm("{ .reg .u64 t; cvta.to.shared.u64 t, %1; cvt.u32.u64 %0, t; }"
        : "=r"(a) : "l"(p));
    return a;
}
__device__ __forceinline__ void ldsm4(uint32_t* r, uint32_t addr) {
    asm volatile("ldmatrix.sync.aligned.m8n8.x4.shared.b16 {%0,%1,%2,%3}, [%4];"
                 : "=r"(r[0]), "=r"(r[1]), "=r"(r[2]), "=r"(r[3]) : "r"(addr));
}
__device__ __forceinline__ void ldsm4t(uint32_t* r, uint32_t addr) {
    asm volatile("ldmatrix.sync.aligned.m8n8.x4.trans.shared.b16 {%0,%1,%2,%3}, [%4];"
                 : "=r"(r[0]), "=r"(r[1]), "=r"(r[2]), "=r"(r[3]) : "r"(addr));
}
__device__ __forceinline__ void mma16816(float* d, const uint32_t* a, const uint32_t* b) {
    asm volatile(
        "mma.sync.aligned.m16n8k16.row.col.f32.f16.f16.f32 "
        "{%0,%1,%2,%3}, {%4,%5,%6,%7}, {%8,%9}, {%0,%1,%2,%3};"
        : "+f"(d[0]), "+f"(d[1]), "+f"(d[2]), "+f"(d[3])
        : "r"(a[0]), "r"(a[1]), "r"(a[2]), "r"(a[3]), "r"(b[0]), "r"(b[1]));
}
__device__ __forceinline__ void cpasync16(uint32_t dst, const void* src, uint32_t n) {
    asm volatile("cp.async.cg.shared.global [%0], [%1], 16, %2;"
                 :: "r"(dst), "l"(src), "r"(n) : "memory");
}
__device__ __forceinline__ void cp_commit() {
    asm volatile("cp.async.commit_group;" ::: "memory");
}
template<int N>
__device__ __forceinline__ void cp_wait() {
    asm volatile("cp.async.wait_group %0;" :: "n"(N) : "memory");
}

__device__ __forceinline__ float gelu_exact(float x) {
    return 0.5f * x * (1.f + erff(x * 0.70710678118654752440f));
}

__device__ __forceinline__ float blockReduceSum(float v) {
    __shared__ float sh[32];
    __shared__ float res;
    int lane = threadIdx.x & 31;
    int wid  = threadIdx.x >> 5;
    #pragma unroll
    for (int o = 16; o > 0; o >>= 1) v += __shfl_down_sync(0xffffffffu, v, o);
    if (lane == 0) sh[wid] = v;
    __syncthreads();
    int nw = (blockDim.x + 31) >> 5;
    v = (threadIdx.x < nw) ? sh[threadIdx.x] : 0.f;
    if (wid == 0) {
        #pragma unroll
        for (int o = 16; o > 0; o >>= 1) v += __shfl_down_sync(0xffffffffu, v, o);
        if (lane == 0) res = v;
    }
    __syncthreads();
    return res;
}

__device__ __forceinline__ uint2 cvt4h(float4 v) {
    __half2 a = __floats2half2_rn(v.x, v.y);
    __half2 b = __floats2half2_rn(v.z, v.w);
    return make_uint2(*reinterpret_cast<uint32_t*>(&a), *reinterpret_cast<uint32_t*>(&b));
}

// ---------------------------------------------------------------------------
// Weight pre-conversion: all 5 weight tensors -> single fp16 plane, ONE launch
// ---------------------------------------------------------------------------
__global__ __launch_bounds__(256)
void cvtw_all_k(const float* __restrict__ spt, const float* __restrict__ inp,
                const float* __restrict__ outp, const float* __restrict__ f1,
                const float* __restrict__ f2, __half* __restrict__ h)
{
    size_t i = ((size_t)blockIdx.x * 256 + threadIdx.x) * 4;
    if (i >= WTOT) return;
    const float* src;
    size_t off;
    if (i < WOFF_INP)       { src = spt;  off = i - WOFF_SPT;  }
    else if (i < WOFF_OUTP) { src = inp;  off = i - WOFF_INP;  }
    else if (i < WOFF_FF1)  { src = outp; off = i - WOFF_OUTP; }
    else if (i < WOFF_FF2)  { src = f1;   off = i - WOFF_FF1;  }
    else                    { src = f2;   off = i - WOFF_FF2;  }
    float4 v = *reinterpret_cast<const float4*>(src + off);
    *reinterpret_cast<uint2*>(h + i) = cvt4h(v);
}

// ---------------------------------------------------------------------------
// cls row init
// ---------------------------------------------------------------------------
__global__ void cls_k(const float* __restrict__ cls_token,
                      const float* __restrict__ pos,
                      float* __restrict__ x)
{
    int i = blockIdx.x * blockDim.x + threadIdx.x;
    if (i >= BATCH * DMODEL) return;
    int b = i / DMODEL, d = i - b * DMODEL;
    x[(long)b * TTOK * DMODEL + d] = cls_token[d] + pos[d];
}

// ---------------------------------------------------------------------------
// HMMA GEMM, fp16 single-pass, cp.async 4-stage pipeline.
// CTA tile 64x128, K-chunk 32, 4 warps (1m x 4n), warp tile 64x32, 4 CTAs/SM.
// ---------------------------------------------------------------------------
#define EPI_STORE_H    0   // store fp16 (feat)
#define EPI_EMBED      1
#define EPI_RESID      2
#define EPI_GELU_H     3
#define EPI_BIAS_RESID 4

#define NTHREADS 128
#define APITCH 80
#define BPITCH 272
#define OFF_A  0
#define OFF_B  5120         // 64*80
#define SBUF   13824        // 5120 + 32*272
#define STAGES 4
#define SMTOT  (STAGES*SBUF)   // 55296; x4 CTAs = 221184 < 228KB

__device__ __forceinline__ void stage_load(uint32_t sb,
                                           const __half* __restrict__ Ah,
                                           const __half* __restrict__ Bh,
                                           int M, int N, int lda,
                                           int rowBase, int colBase, int s, int tid)
{
    const int k0 = s << 5;
    // A: 64 rows x 64B; 256 16B chunks / 128 threads = 2 each
    {
        int row  = tid >> 1;
        int half = tid & 1;
        int gr   = rowBase + row;
        uint32_t nbytes = (gr < M) ? 16u : 0u;
        int grs = (gr < M) ? gr : (M - 1);
        size_t gbase = (size_t)grs * lda + k0 + half * 16;
        uint32_t sbase = (uint32_t)(row * APITCH + half * 32);
        cpasync16(sb + OFF_A + sbase,      Ah + gbase,     nbytes);
        cpasync16(sb + OFF_A + sbase + 16, Ah + gbase + 8, nbytes);
    }
    // B: 32 rows x 256B; 512 chunks / 128 threads = 4 each
    #pragma unroll
    for (int i = 0; i < 4; i++) {
        int idx = tid + i * 128;
        int row = idx >> 4;
        int seg = idx & 15;
        size_t goff = (size_t)(k0 + row) * N + colBase + seg * 8;
        uint32_t so = (uint32_t)(row * BPITCH + seg * 16);
        cpasync16(sb + OFF_B + so, Bh + goff, 16u);
    }
}

__device__ __forceinline__ void compute_chunk(uint32_t sbuf, int lane, int wn,
                                              float acc[4][4][4])
{
    #pragma unroll
    for (int k16 = 0; k16 < 32; k16 += 16) {
        const uint32_t arow = (uint32_t)((lane & 7) + (lane & 8));
        const uint32_t aoff = arow * APITCH + (uint32_t)(k16 + ((lane & 16) >> 1)) * 2;
        const uint32_t brow = (uint32_t)(k16 + (lane & 7) + ((lane & 16) >> 1));
        const uint32_t boff = brow * BPITCH + (uint32_t)(wn + (lane & 8)) * 2;

        uint32_t bH[2][4];
        ldsm4t(bH[0], sbuf + OFF_B + boff);
        ldsm4t(bH[1], sbuf + OFF_B + boff + 32);

        #pragma unroll
        for (int mb = 0; mb < 4; mb++) {
            uint32_t a[4];
            ldsm4(a, sbuf + OFF_A + aoff + mb * 16 * APITCH);
            #pragma unroll
            for (int nb = 0; nb < 4; nb++) {
                uint32_t bb[2] = { bH[nb >> 1][nb & 1], bH[nb >> 1][(nb & 1) + 2] };
                mma16816(acc[mb][nb], a, bb);
            }
        }
    }
}

template<int EPI>
__global__ __launch_bounds__(NTHREADS, 4)
void mmagemm_k(const __half* __restrict__ Ah, const __half* __restrict__ Bh,
               void* __restrict__ Cv,
               const float* __restrict__ bias, const float* __restrict__ extra,
               int M, int N, int K)
{
    extern __shared__ char smem[];
    const uint32_t sbase = smem_u32(smem);
    const int tid  = threadIdx.x;
    const int lane = tid & 31;
    const int wid  = tid >> 5;
    const int wn   = (wid & 3) * 32;    // 4 n-warps, 1 m-warp
    const int rowBase = blockIdx.y * 64;
    const int colBase = blockIdx.x * 128;
    const int nc = K >> 5;

    float acc[4][4][4];
    #pragma unroll
    for (int a = 0; a < 4; a++)
        #pragma unroll
        for (int b = 0; b < 4; b++)
            #pragma unroll
            for (int c = 0; c < 4; c++) acc[a][b][c] = 0.f;

    #pragma unroll
    for (int s = 0; s < STAGES - 1; s++) {
        if (s < nc)
            stage_load(sbase + s * SBUF, Ah, Bh, M, N, K, rowBase, colBase, s, tid);
        cp_commit();
    }

    for (int c = 0; c < nc; c++) {
        cp_wait<STAGES - 2>();
        __syncthreads();
        int s = c + STAGES - 1;
        if (s < nc)
            stage_load(sbase + (s % STAGES) * SBUF, Ah, Bh, M, N, K,
                       rowBase, colBase, s, tid);
        cp_commit();
        compute_chunk(sbase + (c % STAGES) * SBUF, lane, wn, acc);
    }

    // ---- epilogue ----
    const int mrow = rowBase + (lane >> 2);
    const int mcol = colBase + wn + ((lane & 3) << 1);
    #pragma unroll
    for (int mi = 0; mi < 4; mi++) {
        #pragma unroll
        for (int hf = 0; hf < 2; hf++) {
            const int row = mrow + mi * 16 + hf * 8;
            if (row >= M) continue;
            #pragma unroll
            for (int ni = 0; ni < 4; ni++) {
                const int col = mcol + ni * 8;
                float v0 = acc[mi][ni][hf * 2];
                float v1 = acc[mi][ni][hf * 2 + 1];
                if (EPI == EPI_STORE_H) {
                    __half* C = (__half*)Cv;
                    *reinterpret_cast<__half2*>(C + (size_t)row * N + col) =
                        __floats2half2_rn(v0, v1);
                } else if (EPI == EPI_EMBED) {
                    float* C = (float*)Cv;
                    int b  = row >> 8;
                    int tl = row & 255;
                    float2 bb = *reinterpret_cast<const float2*>(bias + col);
                    float2 pp = *reinterpret_cast<const float2*>(extra + (size_t)(tl + 1) * N + col);
                    *reinterpret_cast<float2*>(C + ((size_t)b * TTOK + 1 + tl) * N + col) =
                        make_float2(v0 + bb.x + pp.x, v1 + bb.y + pp.y);
                } else if (EPI == EPI_RESID) {
                    float* C = (float*)Cv;
                    float2* o = reinterpret_cast<float2*>(C + (size_t)row * N + col);
                    float2 cc = *o;
                    *o = make_float2(cc.x + v0, cc.y + v1);
                } else if (EPI == EPI_GELU_H) {
                    __half* Hh = (__half*)Cv;
                    float2 bb = *reinterpret_cast<const float2*>(bias + col);
                    __half2 g = __floats2half2_rn(gelu_exact(v0 + bb.x),
                                                  gelu_exact(v1 + bb.y));
                    *reinterpret_cast<__half2*>(Hh + (size_t)row * N + col) = g;
                } else if (EPI == EPI_BIAS_RESID) {
                    float* C = (float*)Cv;
                    float2 bb = *reinterpret_cast<const float2*>(bias + col);
                    float2* o = reinterpret_cast<float2*>(C + (size_t)row * N + col);
                    float2 cc = *o;
                    *o = make_float2(cc.x + v0 + bb.x, cc.y + v1 + bb.y);
                }
            }
        }
    }
}

// ---------------------------------------------------------------------------
// Shifted-patch extraction + LayerNorm -> fp16 plane
// ---------------------------------------------------------------------------
__global__ __launch_bounds__(256)
void patchln_k(const float* __restrict__ img,
               const float* __restrict__ ln_g,
               const float* __restrict__ ln_b,
               __half* __restrict__ ph)
{
    const int blk = blockIdx.x;
    const int b   = blk >> 8;
    const int pt  = blk & 255;
    const int phh = pt >> 4;
    const int pw  = pt & 15;

    __shared__ float vals[PD];

    const int sh_tab[5] = {0, 0, 0, 1, -1};
    const int sw_tab[5] = {0, 1, -1, 0, 0};

    float s = 0.f, ss = 0.f;
    for (int f = threadIdx.x; f < PD; f += 256) {
        int py  = f / (PSZ * C5);
        int rem = f - py * (PSZ * C5);
        int px  = rem / C5;
        int c   = rem - px * C5;
        int g   = c / CIN;
        int ch  = c - g * CIN;
        int row = phh * PSZ + py - sh_tab[g];
        int col = pw * PSZ + px - sw_tab[g];
        float v = 0.f;
        if (row >= 0 && row < IMG && col >= 0 && col < IMG)
            v = img[(((long)b * CIN + ch) * IMG + row) * IMG + col];
        vals[f] = v;
        s  += v;
        ss += v * v;
    }
    float tsum  = blockReduceSum(s);
    float tsum2 = blockReduceSum(ss);
    float mean  = tsum * (1.f / PD);
    float var   = tsum2 * (1.f / PD) - mean * mean;
    float rstd  = rsqrtf(var + 1e-5f);
    __syncthreads();
    size_t rowoff = (size_t)blk * PD;
    for (int f = threadIdx.x; f < PD; f += 256) {
        float y = (vals[f] - mean) * rstd * ln_g[f] + ln_b[f];
        ph[rowoff + f] = __float2half_rn(y);
    }
}

// ---------------------------------------------------------------------------
__global__ void lb_k(const float* __restrict__ lbin, float* __restrict__ lbout)
{
    int d = blockIdx.x * blockDim.x + threadIdx.x;
    if (d >= DMODEL) return;
    float v[DEPTH];
    float m = -1e30f;
    #pragma unroll
    for (int i = 0; i < DEPTH; i++) { v[i] = lbin[i * DMODEL + d]; m = fmaxf(m, v[i]); }
    float s = 0.f;
    #pragma unroll
    for (int i = 0; i < DEPTH; i++) { v[i] = expf(v[i] - m); s += v[i]; }
    float inv = 1.f / s;
    float c = 0.f;
    float c0 = v[0] * inv;
    #pragma unroll
    for (int i = 0; i < DEPTH; i++) { c += v[i] * inv; lbout[i * DMODEL + d] = c - c0; }
}

// RMSNorm -> fp16 plane
__global__ __launch_bounds__(256)
void rmsnorm_k(const float* __restrict__ x, __half* __restrict__ yh)
{
    const long row = blockIdx.x;
    const float* xr = x + row * DMODEL;
    float s = 0.f;
    for (int i = threadIdx.x; i < DMODEL; i += 256) { float v = xr[i]; s += v * v; }
    float tot = blockReduceSum(s);
    float r = rsqrtf(tot * (1.f / DMODEL) + 1e-6f);
    size_t off = (size_t)row * DMODEL;
    for (int i = threadIdx.x; i < DMODEL; i += 256)
        yh[off + i] = __float2half_rn(xr[i] * r);
}

// hGRU2 scan (reads fp16 feat) -> fp16 plane
__global__ __launch_bounds__(256)
void hgru_k(const __half* __restrict__ feat, const float* __restrict__ lb,
            __half* __restrict__ oh)
{
    int e = blockIdx.x * blockDim.x + threadIdx.x;
    if (e >= TTOK * NHEAD) return;
    int t = e / NHEAD;
    int h = e - t * NHEAD;

    float lb0 = lb[2 * h];
    float lb1 = lb[2 * h + 1];
    float S00 = 0.f, S01 = 0.f, S10 = 0.f, S11 = 0.f;

    #pragma unroll 1
    for (int n = 0; n < BATCH; n++) {
        const __half* r = feat + (size_t)(n * TTOK + t) * (3 * DMODEL);
        float2 vv = __half22float2(*(const __half2*)(r + 2 * h));
        float2 qq = __half22float2(*(const __half2*)(r + DMODEL + 2 * h));
        float2 ff = __half22float2(*(const __half2*)(r + 2 * DMODEL + 2 * h));
        float v0 = gelu_exact(vv.x), v1 = gelu_exact(vv.y);
        float q0 = gelu_exact(qq.x), q1 = gelu_exact(qq.y);
        float s0 = 1.f / (1.f + expf(-ff.x));
        float s1 = 1.f / (1.f + expf(-ff.y));
        float lam0 = lb0 + (1.f - lb0) * s0;
        float lam1 = lb1 + (1.f - lb1) * s1;
        float k0 = 1.f - lam0, k1 = 1.f - lam1;
        S00 = lam0 * S00 + k0 * v0;  S01 = lam0 * S01 + k0 * v1;
        S10 = lam1 * S10 + k1 * v0;  S11 = lam1 * S11 + k1 * v1;
        float o0 = q0 * S00 + q1 * S10;
        float o1 = q0 * S01 + q1 * S11;
        __half2 p = __floats2half2_rn(o0, o1);
        *reinterpret_cast<__half2*>(oh + (size_t)(n * TTOK + t) * DMODEL + 2 * h) = p;
    }
}

__global__ __launch_bounds__(256)
void final_k(const float* __restrict__ x,
             const float* __restrict__ g, const float* __restrict__ bvec,
             float* __restrict__ cls)
{
    int b = blockIdx.x;
    const float* xr = x + (long)b * TTOK * DMODEL;
    __shared__ float y[DMODEL];
    float s = 0.f, ss = 0.f;
    for (int i = threadIdx.x; i < DMODEL; i += 256) {
        float v = xr[i];
        y[i] = v;
        s  += v;
        ss += v * v;
    }
    float tsum  = blockReduceSum(s);
    float tsum2 = blockReduceSum(ss);
    float rstd1 = rsqrtf(tsum2 * (1.f / DMODEL) + 1e-6f);
    float mean  = rstd1 * tsum * (1.f / DMODEL);
    float ez2   = rstd1 * rstd1 * tsum2 * (1.f / DMODEL);
    float var   = ez2 - mean * mean;
    float rstd2 = rsqrtf(var + 1e-5f);
    __syncthreads();
    for (int i = threadIdx.x; i < DMODEL; i += 256) {
        float z = y[i] * rstd1;
        cls[(long)b * DMODEL + i] = (z - mean) * rstd2 * g[i] + bvec[i];
    }
}

__global__ __launch_bounds__(256)
void head_k(const float* __restrict__ cls, const float* __restrict__ w,
            const float* __restrict__ bias, float* __restrict__ out)
{
    int idx = blockIdx.x * blockDim.x + threadIdx.x;
    if (idx >= BATCH * NCLS) return;
    int b = idx / NCLS, c = idx - b * NCLS;
    const float* xr = cls + (long)b * DMODEL;
    float s = bias[c];
    #pragma unroll 4
    for (int k = 0; k < DMODEL; k++)
        s = fmaf(xr[k], w[(long)k * NCLS + c], s);
    out[idx] = s;
}

// ---------------------------------------------------------------------------
// Launch
// ---------------------------------------------------------------------------
extern "C" void kernel_launch(void* const* d_in, const int* in_sizes, int n_in,
                              void* d_out, int out_size)
{
    const float* img          = (const float*)d_in[0];
    const float* spt_ln_g     = (const float*)d_in[1];
    const float* spt_ln_b     = (const float*)d_in[2];
    const float* spt_w        = (const float*)d_in[3];
    const float* spt_b        = (const float*)d_in[4];
    const float* pos_emb      = (const float*)d_in[5];
    const float* cls_token    = (const float*)d_in[6];
    const float* lower_bounds = (const float*)d_in[7];
    const float* in_proj_w    = (const float*)d_in[8];
    const float* out_proj_w   = (const float*)d_in[9];
    const float* ff_w1        = (const float*)d_in[10];
    const float* ff_b1        = (const float*)d_in[11];
    const float* ff_w2        = (const float*)d_in[12];
    const float* ff_b2        = (const float*)d_in[13];
    const float* head_ln_g    = (const float*)d_in[14];
    const float* head_ln_b    = (const float*)d_in[15];
    const float* head_w       = (const float*)d_in[16];
    const float* head_b       = (const float*)d_in[17];

    __half *wh, *ph, *xnh, *oh, *hmh, *feat;
    float *x, *lb, *cls;
    cudaGetSymbolAddress((void**)&wh,   g_wh);
    cudaGetSymbolAddress((void**)&ph,   g_ph);
    cudaGetSymbolAddress((void**)&xnh,  g_xnh);
    cudaGetSymbolAddress((void**)&oh,   g_oh);
    cudaGetSymbolAddress((void**)&hmh,  g_hmh);
    cudaGetSymbolAddress((void**)&feat, g_feat);
    cudaGetSymbolAddress((void**)&x,    g_x);
    cudaGetSymbolAddress((void**)&lb,   g_lb);
    cudaGetSymbolAddress((void**)&cls,  g_cls);

    static bool attr_done = false;
    if (!attr_done) {
        cudaFuncSetAttribute(mmagemm_k<EPI_STORE_H>,    cudaFuncAttributeMaxDynamicSharedMemorySize, SMTOT);
        cudaFuncSetAttribute(mmagemm_k<EPI_EMBED>,      cudaFuncAttributeMaxDynamicSharedMemorySize, SMTOT);
        cudaFuncSetAttribute(mmagemm_k<EPI_RESID>,      cudaFuncAttributeMaxDynamicSharedMemorySize, SMTOT);
        cudaFuncSetAttribute(mmagemm_k<EPI_GELU_H>,     cudaFuncAttributeMaxDynamicSharedMemorySize, SMTOT);
        cudaFuncSetAttribute(mmagemm_k<EPI_BIAS_RESID>, cudaFuncAttributeMaxDynamicSharedMemorySize, SMTOT);
        attr_done = true;
    }

    patchln_k<<<NROWS_EMBED, 256>>>(img, spt_ln_g, spt_ln_b, ph);
    cvtw_all_k<<<(int)((WTOT / 4 + 255) / 256), 256>>>(spt_w, in_proj_w, out_proj_w,
                                                       ff_w1, ff_w2, wh);
    cls_k<<<(BATCH * DMODEL + 255) / 256, 256>>>(cls_token, pos_emb, x);
    {
        dim3 grid(DMODEL / 128, NROWS_EMBED / 64);
        mmagemm_k<EPI_EMBED><<<grid, NTHREADS, SMTOT>>>(
            ph, wh + WOFF_SPT, x, spt_b, pos_emb, NROWS_EMBED, DMODEL, PD);
    }
    lb_k<<<(DMODEL + 255) / 256, 256>>>(lower_bounds, lb);

    for (int i = 0; i < DEPTH; i++) {
        rmsnorm_k<<<NT, 256>>>(x, xnh);
        {
            dim3 grid((3 * DMODEL) / 128, (NT + 63) / 64);
            mmagemm_k<EPI_STORE_H><<<grid, NTHREADS, SMTOT>>>(
                xnh, wh + WOFF_INP + (size_t)i * DMODEL * 3 * DMODEL,
                feat, nullptr, nullptr, NT, 3 * DMODEL, DMODEL);
        }
        hgru_k<<<(TTOK * NHEAD + 255) / 256, 256>>>(feat, lb + (size_t)i * DMODEL, oh);
        {
            dim3 grid(DMODEL / 128, (NT + 63) / 64);
            mmagemm_k<EPI_RESID><<<grid, NTHREADS, SMTOT>>>(
                oh, wh + WOFF_OUTP + (size_t)i * DMODEL * DMODEL,
                x, nullptr, nullptr, NT, DMODEL, DMODEL);
        }
        rmsnorm_k<<<NT, 256>>>(x, xnh);
        {
            dim3 grid(MLP / 128, (NT + 63) / 64);
            mmagemm_k<EPI_GELU_H><<<grid, NTHREADS, SMTOT>>>(
                xnh, wh + WOFF_FF1 + (size_t)i * DMODEL * MLP,
                hmh, ff_b1 + (size_t)i * MLP, nullptr, NT, MLP, DMODEL);
        }
        {
            dim3 grid(DMODEL / 128, (NT + 63) / 64);
            mmagemm_k<EPI_BIAS_RESID><<<grid, NTHREADS, SMTOT>>>(
                hmh, wh + WOFF_FF2 + (size_t)i * MLP * DMODEL,
                x, ff_b2 + (size_t)i * DMODEL, nullptr, NT, DMODEL, MLP);
        }
    }

    final_k<<<BATCH, 256>>>(x, head_ln_g, head_ln_b, cls);
    head_k<<<(BATCH * NCLS + 255) / 256, 256>>>(cls, head_w, head_b, (float*)d_out);
}